// round 1
// baseline (speedup 1.0000x reference)
#include <cuda_runtime.h>
#include <cuda_bf16.h>

#define Bv 64
#define Tv 100
#define Av 8732
#define TG 10          // targets per block in K1 (Tv % TG == 0)

// Scratch: best anchor index per (b, t). Fully rewritten by K1 every launch.
__device__ int g_best_t[Bv * Tv];

// Decide whether candidate (i_n/d_n, idx x_n) beats current (i_c/d_c, idx x_c)
// under "larger rounded quotient wins; exact tie -> lower index".
// Cross-multiply in fp32 with a relative margin; ambiguous cases resolved with
// exact IEEE divisions (rare), reproducing jnp.argmax bit-semantics.
__device__ __forceinline__ bool better(float i_n, float d_n, int x_n,
                                        float i_c, float d_c, int x_c) {
    float pn = __fmul_rn(i_n, d_c);
    float pc = __fmul_rn(i_c, d_n);
    if (pn > __fmul_rn(pc, 1.00001f)) return true;
    if (pc > __fmul_rn(pn, 1.00001f)) return false;
    // ambiguous: compare exactly-rounded quotients (what JAX compares)
    float qn = __fdiv_rn(i_n, d_n);
    float qc = __fdiv_rn(i_c, d_c);
    if (qn > qc) return true;
    if (qn < qc) return false;
    return x_n < x_c;   // tie -> lowest index (jnp.argmax picks first)
}

// K1: for each (b, t) find argmax over anchors of iou(t, a).
// Grid: (Tv/TG, Bv), block 256. Each thread strides anchors, keeps TG
// register-resident running bests; warp shfl + smem reduce at the end.
__global__ __launch_bounds__(256) void k_best_anchor(
        const float* __restrict__ targets,
        const float* __restrict__ anchors) {
    const int b  = blockIdx.y;
    const int t0 = blockIdx.x * TG;

    float bx1[TG], by1[TG], bx2[TG], by2[TG], ab[TG];
#pragma unroll
    for (int i = 0; i < TG; i++) {
        const float* tp = targets + ((size_t)b * Tv + (t0 + i)) * 5;
        bx1[i] = __ldg(tp + 0); by1[i] = __ldg(tp + 1);
        bx2[i] = __ldg(tp + 2); by2[i] = __ldg(tp + 3);
        ab[i]  = __fmul_rn(__fsub_rn(bx2[i], bx1[i]),
                           __fsub_rn(by2[i], by1[i]));
    }

    float ci[TG], cd[TG]; int cx[TG];
#pragma unroll
    for (int i = 0; i < TG; i++) { ci[i] = 0.f; cd[i] = 1.f; cx[i] = threadIdx.x; }

    for (int a = threadIdx.x; a < Av; a += 256) {
        float4 an = __ldg((const float4*)anchors + a);   // cx, cy, w, h
        float hw  = __fmul_rn(an.z, 0.5f), hh = __fmul_rn(an.w, 0.5f);
        float ax1 = __fsub_rn(an.x, hw),  ay1 = __fsub_rn(an.y, hh);
        float ax2 = __fadd_rn(an.x, hw),  ay2 = __fadd_rn(an.y, hh);
        float aa  = __fmul_rn(__fsub_rn(ax2, ax1), __fsub_rn(ay2, ay1));
#pragma unroll
        for (int i = 0; i < TG; i++) {
            float dx = fmaxf(__fsub_rn(fminf(bx2[i], ax2), fmaxf(bx1[i], ax1)), 0.f);
            float dy = fmaxf(__fsub_rn(fminf(by2[i], ay2), fmaxf(by1[i], ay1)), 0.f);
            float inter = __fmul_rn(dx, dy);
            if (inter > 0.f) {
                float denom = __fsub_rn(__fadd_rn(ab[i], aa), inter);
                if (better(inter, denom, a, ci[i], cd[i], cx[i])) {
                    ci[i] = inter; cd[i] = denom; cx[i] = a;
                }
            }
        }
    }

    __shared__ float s_i[TG][8], s_d[TG][8];
    __shared__ int   s_x[TG][8];
    const int lane = threadIdx.x & 31, w = threadIdx.x >> 5;
#pragma unroll
    for (int i = 0; i < TG; i++) {
        float ii = ci[i], dd = cd[i]; int xx = cx[i];
#pragma unroll
        for (int off = 16; off; off >>= 1) {
            float oi = __shfl_down_sync(0xffffffffu, ii, off);
            float od = __shfl_down_sync(0xffffffffu, dd, off);
            int   ox = __shfl_down_sync(0xffffffffu, xx, off);
            if (better(oi, od, ox, ii, dd, xx)) { ii = oi; dd = od; xx = ox; }
        }
        if (lane == 0) { s_i[i][w] = ii; s_d[i][w] = dd; s_x[i][w] = xx; }
    }
    __syncthreads();
    if (threadIdx.x < TG) {
        const int i = threadIdx.x;
        float ii = s_i[i][0], dd = s_d[i][0]; int xx = s_x[i][0];
#pragma unroll
        for (int wv = 1; wv < 8; wv++)
            if (better(s_i[i][wv], s_d[i][wv], s_x[i][wv], ii, dd, xx)) {
                ii = s_i[i][wv]; dd = s_d[i][wv]; xx = s_x[i][wv];
            }
        g_best_t[b * Tv + t0 + i] = xx;
    }
}

// K2: per (b, a): argmax over t, forced-match override, loc encode + conf.
// Grid: (ceil(A/256), Bv), block 256.
__global__ __launch_bounds__(256) void k_match(
        const float* __restrict__ targets,
        const float* __restrict__ anchors,
        float* __restrict__ out) {
    __shared__ float4 sbox[Tv];
    __shared__ float  sarea[Tv];
    __shared__ float  slab[Tv];
    __shared__ int    sbest[Tv];

    const int b   = blockIdx.y;
    const int tid = threadIdx.x;
    if (tid < Tv) {
        const float* tp = targets + ((size_t)b * Tv + tid) * 5;
        float x1 = tp[0], y1 = tp[1], x2 = tp[2], y2 = tp[3];
        sbox[tid]  = make_float4(x1, y1, x2, y2);
        sarea[tid] = __fmul_rn(__fsub_rn(x2, x1), __fsub_rn(y2, y1));
        slab[tid]  = tp[4];
        sbest[tid] = g_best_t[b * Tv + tid];
    }
    __syncthreads();

    const int a = blockIdx.x * blockDim.x + tid;
    if (a >= Av) return;

    float4 an = __ldg((const float4*)anchors + a);
    float hw  = __fmul_rn(an.z, 0.5f), hh = __fmul_rn(an.w, 0.5f);
    float ax1 = __fsub_rn(an.x, hw),  ay1 = __fsub_rn(an.y, hh);
    float ax2 = __fadd_rn(an.x, hw),  ay2 = __fadd_rn(an.y, hh);
    float aa  = __fmul_rn(__fsub_rn(ax2, ax1), __fsub_rn(ay2, ay1));

    float ci = 0.f, cd = 1.f; int ct = 0;
    int forced = -1;
#pragma unroll 5
    for (int t = 0; t < Tv; t++) {
        float4 bx = sbox[t];
        float dx = fmaxf(__fsub_rn(fminf(bx.z, ax2), fmaxf(bx.x, ax1)), 0.f);
        float dy = fmaxf(__fsub_rn(fminf(bx.w, ay2), fmaxf(bx.y, ay1)), 0.f);
        float inter = __fmul_rn(dx, dy);
        if (inter > 0.f) {
            float denom = __fsub_rn(__fadd_rn(sarea[t], aa), inter);
            if (better(inter, denom, t, ci, cd, ct)) { ci = inter; cd = denom; ct = t; }
        }
        if (sbest[t] == a) forced = t;   // duplicates: last write wins
    }

    int gt, conf;
    if (forced >= 0) {
        gt = forced;                       // overlap forced to 1.0 >= THR
        conf = (int)slab[gt] + 1;
    } else {
        gt = ct;
        float q = __fdiv_rn(ci, cd);       // single exact div per anchor
        conf = (q < 0.5f) ? 0 : ((int)slab[gt] + 1);
    }

    float4 m  = sbox[gt];
    float mcx = (m.x + m.z) * 0.5f, mcy = (m.y + m.w) * 0.5f;
    float mw  = m.z - m.x,          mh  = m.w - m.y;
    float l0  = (mcx - an.x) / (0.1f * an.z);
    float l1  = (mcy - an.y) / (0.1f * an.w);
    float l2  = logf(mw / an.z) / 0.2f;
    float l3  = logf(mh / an.w) / 0.2f;

    size_t base = ((size_t)b * Av + a) * 4;
    out[base + 0] = l0; out[base + 1] = l1;
    out[base + 2] = l2; out[base + 3] = l3;
    out[(size_t)Bv * Av * 4 + (size_t)b * Av + a] = (float)conf;
}

extern "C" void kernel_launch(void* const* d_in, const int* in_sizes, int n_in,
                              void* d_out, int out_size) {
    const float* targets = (const float*)d_in[0];   // (B, T, 5) f32
    const float* anchors = (const float*)d_in[1];   // (A, 4)   f32
    float* out = (float*)d_out;                     // loc (B*A*4) then conf (B*A)

    dim3 g1(Tv / TG, Bv);
    k_best_anchor<<<g1, 256>>>(targets, anchors);

    dim3 g2((Av + 255) / 256, Bv);
    k_match<<<g2, 256>>>(targets, anchors, out);
}

// round 2
// speedup vs baseline: 1.6295x; 1.6295x over previous
#include <cuda_runtime.h>
#include <cuda_bf16.h>

#define Bv 64
#define Tv 100
#define Av 8732
#define TG 5           // targets per block in K1 (Tv % TG == 0)

// forced[b*A+a] = t of the (last) target whose best anchor is a, else -1.
__device__ int g_forced[Bv * Av];

// exact max(x, 0) on the fma pipe: 0.5*(x+|x|)  (exact for all finite x)
__device__ __forceinline__ float clamp0(float x) {
    return __fmul_rn(__fadd_rn(x, fabsf(x)), 0.5f);
}

// K0: fill g_forced with -1 (int4-vectorized).
__global__ __launch_bounds__(256) void k_fill() {
    const int n4 = (Bv * Av) / 4;      // 139712, exact
    int i = blockIdx.x * blockDim.x + threadIdx.x;
    if (i < n4) ((int4*)g_forced)[i] = make_int4(-1, -1, -1, -1);
}

// K1: per (b, t) argmax over anchors of iou(t, a); winner scattered via
// atomicMax into g_forced (max t == last-write-wins, matching JAX scatter).
// Grid: (Tv/TG, Bv), block 256; threads stride anchors.
__global__ __launch_bounds__(256) void k_best_anchor(
        const float* __restrict__ targets,
        const float* __restrict__ anchors) {
    const int b  = blockIdx.y;
    const int t0 = blockIdx.x * TG;

    float bx1[TG], by1[TG], bx2[TG], by2[TG], ab[TG];
#pragma unroll
    for (int i = 0; i < TG; i++) {
        const float* tp = targets + ((size_t)b * Tv + (t0 + i)) * 5;
        bx1[i] = __ldg(tp + 0); by1[i] = __ldg(tp + 1);
        bx2[i] = __ldg(tp + 2); by2[i] = __ldg(tp + 3);
        ab[i]  = __fmul_rn(__fsub_rn(bx2[i], bx1[i]),
                           __fsub_rn(by2[i], by1[i]));
    }

    // running best: exact rounded quotient q, index x, filter slope s
    float q[TG], s[TG]; int x[TG];
#pragma unroll
    for (int i = 0; i < TG; i++) { q[i] = 0.f; s[i] = 0.f; x[i] = threadIdx.x; }

    for (int a = threadIdx.x; a < Av; a += 256) {
        float4 an = __ldg((const float4*)anchors + a);   // cx, cy, w, h
        float hw  = __fmul_rn(an.z, 0.5f), hh = __fmul_rn(an.w, 0.5f);
        float ax1 = __fsub_rn(an.x, hw),  ay1 = __fsub_rn(an.y, hh);
        float ax2 = __fadd_rn(an.x, hw),  ay2 = __fadd_rn(an.y, hh);
        float aa  = __fmul_rn(__fsub_rn(ax2, ax1), __fsub_rn(ay2, ay1));
#pragma unroll
        for (int i = 0; i < TG; i++) {
            float dx = clamp0(__fsub_rn(fminf(bx2[i], ax2), fmaxf(bx1[i], ax1)));
            float dy = clamp0(__fsub_rn(fminf(by2[i], ay2), fmaxf(by1[i], ay1)));
            float inter = __fmul_rn(dx, dy);
            float sab   = __fadd_rn(ab[i], aa);
            if (inter > __fmul_rn(s[i], sab)) {          // safe reject filter
                float qc = __fdiv_rn(inter, __fsub_rn(sab, inter));
                if (qc > q[i]) {                          // exact JAX compare
                    q[i] = qc; x[i] = a;
                    s[i] = __fmul_rn(__fdividef(qc, __fadd_rn(1.f, qc)), 0.99999f);
                }
            }
        }
    }

    __shared__ float s_q[TG][8];
    __shared__ int   s_x[TG][8];
    const int lane = threadIdx.x & 31, w = threadIdx.x >> 5;
#pragma unroll
    for (int i = 0; i < TG; i++) {
        float qq = q[i]; int xx = x[i];
#pragma unroll
        for (int off = 16; off; off >>= 1) {
            float qo = __shfl_down_sync(0xffffffffu, qq, off);
            int   xo = __shfl_down_sync(0xffffffffu, xx, off);
            if (qo > qq || (qo == qq && xo < xx)) { qq = qo; xx = xo; }
        }
        if (lane == 0) { s_q[i][w] = qq; s_x[i][w] = xx; }
    }
    __syncthreads();
    if (threadIdx.x < TG) {
        const int i = threadIdx.x;
        float qq = s_q[i][0]; int xx = s_x[i][0];
#pragma unroll
        for (int wv = 1; wv < 8; wv++) {
            float qo = s_q[i][wv]; int xo = s_x[i][wv];
            if (qo > qq || (qo == qq && xo < xx)) { qq = qo; xx = xo; }
        }
        atomicMax(&g_forced[b * Av + xx], t0 + i);   // last (max) t wins
    }
}

// K2: per (b, a): argmax over t, forced override, loc encode + conf.
// Grid: (ceil(A/256), Bv), block 256.
__global__ __launch_bounds__(256) void k_match(
        const float* __restrict__ targets,
        const float* __restrict__ anchors,
        float* __restrict__ out) {
    __shared__ float4 sbox[Tv];
    __shared__ float  sarea[Tv];
    __shared__ float  slab[Tv];

    const int b   = blockIdx.y;
    const int tid = threadIdx.x;
    if (tid < Tv) {
        const float* tp = targets + ((size_t)b * Tv + tid) * 5;
        float x1 = tp[0], y1 = tp[1], x2 = tp[2], y2 = tp[3];
        sbox[tid]  = make_float4(x1, y1, x2, y2);
        sarea[tid] = __fmul_rn(__fsub_rn(x2, x1), __fsub_rn(y2, y1));
        slab[tid]  = tp[4];
    }
    __syncthreads();

    const int a = blockIdx.x * blockDim.x + tid;
    if (a >= Av) return;

    float4 an = __ldg((const float4*)anchors + a);
    float hw  = __fmul_rn(an.z, 0.5f), hh = __fmul_rn(an.w, 0.5f);
    float ax1 = __fsub_rn(an.x, hw),  ay1 = __fsub_rn(an.y, hh);
    float ax2 = __fadd_rn(an.x, hw),  ay2 = __fadd_rn(an.y, hh);
    float aa  = __fmul_rn(__fsub_rn(ax2, ax1), __fsub_rn(ay2, ay1));

    float q = 0.f, s = 0.f; int ct = 0;
#pragma unroll 4
    for (int t = 0; t < Tv; t++) {
        float4 bx = sbox[t];                                 // warp-broadcast LDS
        float dx = clamp0(__fsub_rn(fminf(bx.z, ax2), fmaxf(bx.x, ax1)));
        float dy = clamp0(__fsub_rn(fminf(bx.w, ay2), fmaxf(bx.y, ay1)));
        float inter = __fmul_rn(dx, dy);
        float sab   = __fadd_rn(sarea[t], aa);
        if (inter > __fmul_rn(s, sab)) {
            float qc = __fdiv_rn(inter, __fsub_rn(sab, inter));
            if (qc > q) {
                q = qc; ct = t;
                s = __fmul_rn(__fdividef(qc, __fadd_rn(1.f, qc)), 0.99999f);
            }
        }
    }

    const int forced = g_forced[b * Av + a];
    int gt, conf;
    if (forced >= 0) {
        gt = forced;                       // overlap forced to 1.0 >= THR
        conf = (int)slab[gt] + 1;
    } else {
        gt = ct;
        conf = (q < 0.5f) ? 0 : ((int)slab[gt] + 1);
    }

    float4 m  = sbox[gt];
    float mcx = (m.x + m.z) * 0.5f, mcy = (m.y + m.w) * 0.5f;
    float mw  = m.z - m.x,          mh  = m.w - m.y;
    float l0  = (mcx - an.x) / (0.1f * an.z);
    float l1  = (mcy - an.y) / (0.1f * an.w);
    float l2  = logf(mw / an.z) / 0.2f;
    float l3  = logf(mh / an.w) / 0.2f;

    size_t base = ((size_t)b * Av + a) * 4;
    out[base + 0] = l0; out[base + 1] = l1;
    out[base + 2] = l2; out[base + 3] = l3;
    out[(size_t)Bv * Av * 4 + (size_t)b * Av + a] = (float)conf;
}

extern "C" void kernel_launch(void* const* d_in, const int* in_sizes, int n_in,
                              void* d_out, int out_size) {
    const float* targets = (const float*)d_in[0];   // (B, T, 5) f32
    const float* anchors = (const float*)d_in[1];   // (A, 4)   f32
    float* out = (float*)d_out;                     // loc (B*A*4) then conf (B*A)

    k_fill<<<(Bv * Av / 4 + 255) / 256, 256>>>();

    dim3 g1(Tv / TG, Bv);
    k_best_anchor<<<g1, 256>>>(targets, anchors);

    dim3 g2((Av + 255) / 256, Bv);
    k_match<<<g2, 256>>>(targets, anchors, out);
}